// round 1
// baseline (speedup 1.0000x reference)
#include <cuda_runtime.h>
#include <math.h>

#define SEQ 2048
#define DIM 2880
#define NH 64
#define NKV 8
#define HD 64
#define QDIM (NH*HD)     // 4096
#define KVDIM (NKV*HD)   // 512
#define WINDOW 128

// Scratch (allocation-free rule: __device__ globals)
__device__ float g_q[SEQ * QDIM];      // 32 MB
__device__ float g_k[SEQ * KVDIM];     // 4 MB
__device__ float g_v[SEQ * KVDIM];     // 4 MB
__device__ float g_attn[SEQ * QDIM];   // 32 MB

// ---------------------------------------------------------------------------
// SGEMM (NT): C[M,N] = A[M,K] @ B[N,K]^T + bias[N]
// 128x128 block tile, BK=8, 256 threads, 8x8 register tile, global prefetch.
// M must be a multiple of 128 and K a multiple of 8 (true here); N is guarded.
// ---------------------------------------------------------------------------
__global__ __launch_bounds__(256) void sgemm_nt(
    const float* __restrict__ A, const float* __restrict__ B,
    const float* __restrict__ bias, float* __restrict__ C,
    int M, int N, int K)
{
    __shared__ float As[8][128];
    __shared__ float Bs[8][128];

    const int tid = threadIdx.x;
    const int bm  = blockIdx.y * 128;
    const int bn  = blockIdx.x * 128;

    // load mapping: each thread loads one float4 of A and one of B per K-step
    const int lr = tid >> 1;          // 0..127
    const int lc = (tid & 1) << 2;    // 0 or 4

    // compute mapping: 16x16 threads, 8x8 micro-tile
    const int tx = tid & 15, ty = tid >> 4;
    const int row0 = ty << 3, col0 = tx << 3;

    const float* Ap = A + (size_t)(bm + lr) * K + lc;
    const int brow = bn + lr;
    const float* Bp = B + (size_t)brow * K + lc;
    const bool bv = (brow < N);

    float acc[8][8];
#pragma unroll
    for (int i = 0; i < 8; i++)
#pragma unroll
        for (int j = 0; j < 8; j++) acc[i][j] = 0.f;

    float4 a4 = *(const float4*)Ap;
    float4 b4 = bv ? *(const float4*)Bp : make_float4(0.f, 0.f, 0.f, 0.f);

    for (int k0 = 0; k0 < K; k0 += 8) {
        As[lc + 0][lr] = a4.x; As[lc + 1][lr] = a4.y;
        As[lc + 2][lr] = a4.z; As[lc + 3][lr] = a4.w;
        Bs[lc + 0][lr] = b4.x; Bs[lc + 1][lr] = b4.y;
        Bs[lc + 2][lr] = b4.z; Bs[lc + 3][lr] = b4.w;
        __syncthreads();

        if (k0 + 8 < K) {   // prefetch next tile while computing this one
            a4 = *(const float4*)(Ap + k0 + 8);
            b4 = bv ? *(const float4*)(Bp + k0 + 8) : make_float4(0.f, 0.f, 0.f, 0.f);
        }

#pragma unroll
        for (int kk = 0; kk < 8; kk++) {
            float ra[8], rb[8];
#pragma unroll
            for (int i = 0; i < 8; i++) ra[i] = As[kk][row0 + i];
#pragma unroll
            for (int j = 0; j < 8; j++) rb[j] = Bs[kk][col0 + j];
#pragma unroll
            for (int i = 0; i < 8; i++)
#pragma unroll
                for (int j = 0; j < 8; j++)
                    acc[i][j] = fmaf(ra[i], rb[j], acc[i][j]);
        }
        __syncthreads();
    }

    // epilogue: bias + store (float4; N % 4 == 0 for all our N)
#pragma unroll
    for (int i = 0; i < 8; i++) {
        const size_t rowoff = (size_t)(bm + row0 + i) * N;
#pragma unroll
        for (int j4 = 0; j4 < 2; j4++) {
            const int n = bn + col0 + j4 * 4;
            if (n < N) {
                float4 o;
                o.x = acc[i][j4 * 4 + 0] + bias[n + 0];
                o.y = acc[i][j4 * 4 + 1] + bias[n + 1];
                o.z = acc[i][j4 * 4 + 2] + bias[n + 2];
                o.w = acc[i][j4 * 4 + 3] + bias[n + 3];
                *(float4*)(C + rowoff + n) = o;
            }
        }
    }
}

// ---------------------------------------------------------------------------
// RoPE, in-place on [SEQ, n_heads, 64]. One thread per rotation pair.
// rope_cache: [SEQ, 128] with cos in [:,0:64), sin in [:,64:128).
// ---------------------------------------------------------------------------
__global__ void rope_kernel(float* __restrict__ t, const float* __restrict__ rope,
                            int n_heads)
{
    const int idx = blockIdx.x * blockDim.x + threadIdx.x;
    const int total = SEQ * n_heads * 32;
    if (idx >= total) return;
    const int d = idx & 31;
    const int h = (idx >> 5) % n_heads;
    const int s = idx / (32 * n_heads);

    const float c1 = rope[s * 128 + d];
    const float c2 = rope[s * 128 + d + 32];
    const float s1 = rope[s * 128 + 64 + d];
    const float s2 = rope[s * 128 + 96 + d];

    float* base = t + ((size_t)s * n_heads + h) * HD;
    const float x1 = base[d];
    const float x2 = base[d + 32];
    base[d]      = x1 * c1 - x2 * s1;
    base[d + 32] = x2 * c2 + x1 * s2;
}

// ---------------------------------------------------------------------------
// Sliding-window attention + sink gating.
// One warp per (query i, head h). Keys j in [max(0, i-127), i] (<=128).
// q: [SEQ, QDIM], k/v: [SEQ, KVDIM], out: [SEQ, QDIM] (head-major inner).
// ---------------------------------------------------------------------------
__global__ __launch_bounds__(128) void attn_kernel(
    const float* __restrict__ q, const float* __restrict__ k,
    const float* __restrict__ v, const float* __restrict__ sinks,
    float* __restrict__ out)
{
    const float scale = 0.16832169945461f;  // (0.1*ln(32)+1)/8
    const int w    = threadIdx.x >> 5;
    const int lane = threadIdx.x & 31;
    const int p = blockIdx.x * 4 + w;       // p = h*SEQ + i
    const int i = p & (SEQ - 1);
    const int h = p >> 11;

    __shared__ float shq[4][64];
    __shared__ float shp[4][128];

    const float* qrow = q + (size_t)i * QDIM + h * HD;
    shq[w][lane]      = qrow[lane];
    shq[w][lane + 32] = qrow[lane + 32];
    __syncwarp();

    const int kvh = h >> 3;
    int start = i - (WINDOW - 1); if (start < 0) start = 0;
    const int cnt = i - start + 1;

    float sc[4];
#pragma unroll
    for (int t = 0; t < 4; t++) {
        const int jj = lane + 32 * t;
        if (jj < cnt) {
            const float4* krow =
                (const float4*)(k + (size_t)(start + jj) * KVDIM + kvh * HD);
            float s = 0.f;
#pragma unroll
            for (int d4 = 0; d4 < 16; d4++) {
                const float4 kk = krow[d4];
                s = fmaf(kk.x, shq[w][d4 * 4 + 0], s);
                s = fmaf(kk.y, shq[w][d4 * 4 + 1], s);
                s = fmaf(kk.z, shq[w][d4 * 4 + 2], s);
                s = fmaf(kk.w, shq[w][d4 * 4 + 3], s);
            }
            sc[t] = s * scale;
        } else {
            sc[t] = -1e30f;
        }
    }

    // warp softmax over <=128 scores
    float m = fmaxf(fmaxf(sc[0], sc[1]), fmaxf(sc[2], sc[3]));
#pragma unroll
    for (int o = 16; o; o >>= 1) m = fmaxf(m, __shfl_xor_sync(0xffffffffu, m, o));

    float e[4], sum = 0.f;
#pragma unroll
    for (int t = 0; t < 4; t++) { e[t] = expf(sc[t] - m); sum += e[t]; }
#pragma unroll
    for (int o = 16; o; o >>= 1) sum += __shfl_xor_sync(0xffffffffu, sum, o);

    const float lse  = m + logf(sum);
    const float sig  = 1.f / (1.f + expf(sinks[h] - lse));  // sigmoid(lse - sink)
    const float wsc  = sig / sum;
#pragma unroll
    for (int t = 0; t < 4; t++) shp[w][lane + 32 * t] = e[t] * wsc;
    __syncwarp();

    // out[d] = sum_j p_j * v[j, d]; lane owns dims {lane, lane+32}
    float acc0 = 0.f, acc1 = 0.f;
    for (int jj = 0; jj < cnt; jj++) {
        const float pj = shp[w][jj];
        const float* vrow = v + (size_t)(start + jj) * KVDIM + kvh * HD;
        acc0 = fmaf(pj, vrow[lane], acc0);
        acc1 = fmaf(pj, vrow[lane + 32], acc1);
    }
    float* orow = out + (size_t)i * QDIM + h * HD;
    orow[lane]      = acc0;
    orow[lane + 32] = acc1;
}

// ---------------------------------------------------------------------------
extern "C" void kernel_launch(void* const* d_in, const int* in_sizes, int n_in,
                              void* d_out, int out_size)
{
    const float* x     = (const float*)d_in[0];
    const float* rope  = (const float*)d_in[1];
    const float* wq_w  = (const float*)d_in[2];
    const float* wq_b  = (const float*)d_in[3];
    const float* wk_w  = (const float*)d_in[4];
    const float* wk_b  = (const float*)d_in[5];
    const float* wv_w  = (const float*)d_in[6];
    const float* wv_b  = (const float*)d_in[7];
    const float* wo_w  = (const float*)d_in[8];
    const float* wo_b  = (const float*)d_in[9];
    const float* sinks = (const float*)d_in[10];
    float* out = (float*)d_out;

    float *q, *k, *v, *attn;
    cudaGetSymbolAddress((void**)&q, g_q);
    cudaGetSymbolAddress((void**)&k, g_k);
    cudaGetSymbolAddress((void**)&v, g_v);
    cudaGetSymbolAddress((void**)&attn, g_attn);

    // QKV projections
    sgemm_nt<<<dim3(QDIM / 128, SEQ / 128), 256>>>(x, wq_w, wq_b, q, SEQ, QDIM, DIM);
    sgemm_nt<<<dim3(KVDIM / 128, SEQ / 128), 256>>>(x, wk_w, wk_b, k, SEQ, KVDIM, DIM);
    sgemm_nt<<<dim3(KVDIM / 128, SEQ / 128), 256>>>(x, wv_w, wv_b, v, SEQ, KVDIM, DIM);

    // RoPE on q (64 heads) and k (8 heads)
    rope_kernel<<<(SEQ * NH * 32 + 255) / 256, 256>>>(q, rope, NH);
    rope_kernel<<<(SEQ * NKV * 32 + 255) / 256, 256>>>(k, rope, NKV);

    // Sliding-window attention with sink gating
    attn_kernel<<<SEQ * NH / 4, 128>>>(q, k, v, sinks, attn);

    // Output projection
    sgemm_nt<<<dim3((DIM + 127) / 128, SEQ / 128), 256>>>(attn, wo_w, wo_b, out, SEQ, DIM, QDIM);
}

// round 2
// speedup vs baseline: 3.1466x; 3.1466x over previous
#include <cuda_runtime.h>
#include <math.h>

#define SEQ 2048
#define DIM 2880
#define NH 64
#define NKV 8
#define HD 64
#define QDIM (NH*HD)     // 4096
#define KVDIM (NKV*HD)   // 512
#define WINDOW 128

// Scratch (allocation-free rule: __device__ globals)
__device__ float g_q[SEQ * QDIM];      // 32 MB
__device__ float g_k[SEQ * KVDIM];     // 4 MB
__device__ float g_v[SEQ * KVDIM];     // 4 MB
__device__ float g_attn[SEQ * QDIM];   // 32 MB

// ---------------------------------------------------------------------------
// tf32 tensor-core GEMM (NT): C[M,N] = A[M,K] @ B[N,K]^T + bias[N]
// mma.sync.m16n8k8.row.col — B[N,K] row-major IS the k-major 'col' operand.
// Block tile 128x128, BK=16, 256 threads = 8 warps (4m x 2n), warp tile 32x64.
// Smem stride 20 floats -> conflict-free fragment loads.
// Requires: M % 128 == 0, K % 16 == 0. N guarded.
// ---------------------------------------------------------------------------
__device__ __forceinline__ unsigned f2tf32(float x) {
    unsigned r;
    asm("cvt.rna.tf32.f32 %0, %1;" : "=r"(r) : "f"(x));
    return r;
}

#define LDS_ 20

__global__ __launch_bounds__(256) void gemm_tf32(
    const float* __restrict__ A, const float* __restrict__ B,
    const float* __restrict__ bias, float* __restrict__ C,
    int M, int N, int K)
{
    __shared__ unsigned As[128 * LDS_];
    __shared__ unsigned Bs[128 * LDS_];

    const int tid  = threadIdx.x;
    const int bm   = blockIdx.y * 128;
    const int bn   = blockIdx.x * 128;
    const int wid  = tid >> 5;
    const int lane = tid & 31;
    const int wm   = (wid & 3) * 32;   // warp m offset in tile
    const int wn   = (wid >> 2) * 64;  // warp n offset in tile
    const int g    = lane >> 2;        // group id 0..7
    const int tg   = lane & 3;         // thread-in-group 0..3

    // global -> smem mapping: 512 float4 per tile, 2 per thread
    const int ar0 = tid >> 1;                 // rows 0..127
    const int ac0 = (tid & 1) * 8;            // k offset 0 or 8
    // each thread loads TWO float4 covering k [ac0, ac0+8)
    const float* Ap = A + (size_t)(bm + ar0) * K + ac0;
    const int brow  = bn + ar0;
    const float* Bp = B + (size_t)brow * K + ac0;
    const bool bv   = (brow < N);

    float acc[2][8][4];
#pragma unroll
    for (int mi = 0; mi < 2; mi++)
#pragma unroll
        for (int ni = 0; ni < 8; ni++)
#pragma unroll
            for (int r = 0; r < 4; r++) acc[mi][ni][r] = 0.f;

    float4 a4a = *(const float4*)Ap;
    float4 a4b = *(const float4*)(Ap + 4);
    float4 b4a = bv ? *(const float4*)Bp : make_float4(0.f,0.f,0.f,0.f);
    float4 b4b = bv ? *(const float4*)(Bp + 4) : make_float4(0.f,0.f,0.f,0.f);

    for (int k0 = 0; k0 < K; k0 += 16) {
        // store (converted to tf32) into smem
        unsigned* asrow = As + ar0 * LDS_ + ac0;
        asrow[0] = f2tf32(a4a.x); asrow[1] = f2tf32(a4a.y);
        asrow[2] = f2tf32(a4a.z); asrow[3] = f2tf32(a4a.w);
        asrow[4] = f2tf32(a4b.x); asrow[5] = f2tf32(a4b.y);
        asrow[6] = f2tf32(a4b.z); asrow[7] = f2tf32(a4b.w);
        unsigned* bsrow = Bs + ar0 * LDS_ + ac0;
        bsrow[0] = f2tf32(b4a.x); bsrow[1] = f2tf32(b4a.y);
        bsrow[2] = f2tf32(b4a.z); bsrow[3] = f2tf32(b4a.w);
        bsrow[4] = f2tf32(b4b.x); bsrow[5] = f2tf32(b4b.y);
        bsrow[6] = f2tf32(b4b.z); bsrow[7] = f2tf32(b4b.w);
        __syncthreads();

        if (k0 + 16 < K) {  // prefetch next tile into registers
            a4a = *(const float4*)(Ap + k0 + 16);
            a4b = *(const float4*)(Ap + k0 + 20);
            if (bv) {
                b4a = *(const float4*)(Bp + k0 + 16);
                b4b = *(const float4*)(Bp + k0 + 20);
            }
        }

#pragma unroll
        for (int ks = 0; ks < 2; ks++) {
            const int kk = ks * 8;
            unsigned a[2][4];
#pragma unroll
            for (int mi = 0; mi < 2; mi++) {
                const int r = wm + mi * 16 + g;
                a[mi][0] = As[r * LDS_ + kk + tg];
                a[mi][1] = As[(r + 8) * LDS_ + kk + tg];
                a[mi][2] = As[r * LDS_ + kk + tg + 4];
                a[mi][3] = As[(r + 8) * LDS_ + kk + tg + 4];
            }
#pragma unroll
            for (int ni = 0; ni < 8; ni++) {
                const int nr = wn + ni * 8 + g;
                const unsigned b0 = Bs[nr * LDS_ + kk + tg];
                const unsigned b1 = Bs[nr * LDS_ + kk + tg + 4];
#pragma unroll
                for (int mi = 0; mi < 2; mi++) {
                    asm volatile(
                        "mma.sync.aligned.m16n8k8.row.col.f32.tf32.tf32.f32 "
                        "{%0,%1,%2,%3}, {%4,%5,%6,%7}, {%8,%9}, {%0,%1,%2,%3};"
                        : "+f"(acc[mi][ni][0]), "+f"(acc[mi][ni][1]),
                          "+f"(acc[mi][ni][2]), "+f"(acc[mi][ni][3])
                        : "r"(a[mi][0]), "r"(a[mi][1]), "r"(a[mi][2]), "r"(a[mi][3]),
                          "r"(b0), "r"(b1));
                }
            }
        }
        __syncthreads();
    }

    // epilogue: bias + store. c0/c1 -> (row, col), (row, col+1); c2/c3 -> row+8
#pragma unroll
    for (int mi = 0; mi < 2; mi++) {
        const int row = bm + wm + mi * 16 + g;
#pragma unroll
        for (int ni = 0; ni < 8; ni++) {
            const int col = bn + wn + ni * 8 + tg * 2;
            if (col < N) {
                const float bx = bias[col], by = bias[col + 1];
                float2 v0 = make_float2(acc[mi][ni][0] + bx, acc[mi][ni][1] + by);
                float2 v1 = make_float2(acc[mi][ni][2] + bx, acc[mi][ni][3] + by);
                *(float2*)(C + (size_t)row * N + col)       = v0;
                *(float2*)(C + (size_t)(row + 8) * N + col) = v1;
            }
        }
    }
}

// ---------------------------------------------------------------------------
// RoPE, in-place on [SEQ, n_heads, 64]. One thread per rotation pair.
// rope_cache: [SEQ, 128] with cos in [:,0:64), sin in [:,64:128).
// ---------------------------------------------------------------------------
__global__ void rope_kernel(float* __restrict__ t, const float* __restrict__ rope,
                            int n_heads)
{
    const int idx = blockIdx.x * blockDim.x + threadIdx.x;
    const int total = SEQ * n_heads * 32;
    if (idx >= total) return;
    const int d = idx & 31;
    const int h = (idx >> 5) % n_heads;
    const int s = idx / (32 * n_heads);

    const float c1 = rope[s * 128 + d];
    const float c2 = rope[s * 128 + d + 32];
    const float s1 = rope[s * 128 + 64 + d];
    const float s2 = rope[s * 128 + 96 + d];

    float* base = t + ((size_t)s * n_heads + h) * HD;
    const float x1 = base[d];
    const float x2 = base[d + 32];
    base[d]      = x1 * c1 - x2 * s1;
    base[d + 32] = x2 * c2 + x1 * s2;
}

// ---------------------------------------------------------------------------
// Sliding-window attention + sink gating.
// One warp per (query i, head h). Keys j in [max(0, i-127), i] (<=128).
// ---------------------------------------------------------------------------
__global__ __launch_bounds__(128) void attn_kernel(
    const float* __restrict__ q, const float* __restrict__ k,
    const float* __restrict__ v, const float* __restrict__ sinks,
    float* __restrict__ out)
{
    const float scale = 0.16832169945461f;  // (0.1*ln(32)+1)/8
    const int w    = threadIdx.x >> 5;
    const int lane = threadIdx.x & 31;
    const int p = blockIdx.x * 4 + w;       // p = h*SEQ + i
    const int i = p & (SEQ - 1);
    const int h = p >> 11;

    __shared__ float shq[4][64];
    __shared__ float shp[4][128];

    const float* qrow = q + (size_t)i * QDIM + h * HD;
    shq[w][lane]      = qrow[lane];
    shq[w][lane + 32] = qrow[lane + 32];
    __syncwarp();

    const int kvh = h >> 3;
    int start = i - (WINDOW - 1); if (start < 0) start = 0;
    const int cnt = i - start + 1;

    float sc[4];
#pragma unroll
    for (int t = 0; t < 4; t++) {
        const int jj = lane + 32 * t;
        if (jj < cnt) {
            const float4* krow =
                (const float4*)(k + (size_t)(start + jj) * KVDIM + kvh * HD);
            float s = 0.f;
#pragma unroll
            for (int d4 = 0; d4 < 16; d4++) {
                const float4 kk = krow[d4];
                s = fmaf(kk.x, shq[w][d4 * 4 + 0], s);
                s = fmaf(kk.y, shq[w][d4 * 4 + 1], s);
                s = fmaf(kk.z, shq[w][d4 * 4 + 2], s);
                s = fmaf(kk.w, shq[w][d4 * 4 + 3], s);
            }
            sc[t] = s * scale;
        } else {
            sc[t] = -1e30f;
        }
    }

    float m = fmaxf(fmaxf(sc[0], sc[1]), fmaxf(sc[2], sc[3]));
#pragma unroll
    for (int o = 16; o; o >>= 1) m = fmaxf(m, __shfl_xor_sync(0xffffffffu, m, o));

    float e[4], sum = 0.f;
#pragma unroll
    for (int t = 0; t < 4; t++) { e[t] = expf(sc[t] - m); sum += e[t]; }
#pragma unroll
    for (int o = 16; o; o >>= 1) sum += __shfl_xor_sync(0xffffffffu, sum, o);

    const float lse  = m + logf(sum);
    const float sig  = 1.f / (1.f + expf(sinks[h] - lse));
    const float wsc  = sig / sum;
#pragma unroll
    for (int t = 0; t < 4; t++) shp[w][lane + 32 * t] = e[t] * wsc;
    __syncwarp();

    float acc0 = 0.f, acc1 = 0.f;
    for (int jj = 0; jj < cnt; jj++) {
        const float pj = shp[w][jj];
        const float* vrow = v + (size_t)(start + jj) * KVDIM + kvh * HD;
        acc0 = fmaf(pj, vrow[lane], acc0);
        acc1 = fmaf(pj, vrow[lane + 32], acc1);
    }
    float* orow = out + (size_t)i * QDIM + h * HD;
    orow[lane]      = acc0;
    orow[lane + 32] = acc1;
}

// ---------------------------------------------------------------------------
extern "C" void kernel_launch(void* const* d_in, const int* in_sizes, int n_in,
                              void* d_out, int out_size)
{
    const float* x     = (const float*)d_in[0];
    const float* rope  = (const float*)d_in[1];
    const float* wq_w  = (const float*)d_in[2];
    const float* wq_b  = (const float*)d_in[3];
    const float* wk_w  = (const float*)d_in[4];
    const float* wk_b  = (const float*)d_in[5];
    const float* wv_w  = (const float*)d_in[6];
    const float* wv_b  = (const float*)d_in[7];
    const float* wo_w  = (const float*)d_in[8];
    const float* wo_b  = (const float*)d_in[9];
    const float* sinks = (const float*)d_in[10];
    float* out = (float*)d_out;

    float *q, *k, *v, *attn;
    cudaGetSymbolAddress((void**)&q, g_q);
    cudaGetSymbolAddress((void**)&k, g_k);
    cudaGetSymbolAddress((void**)&v, g_v);
    cudaGetSymbolAddress((void**)&attn, g_attn);

    // QKV projections (tensor cores, tf32)
    gemm_tf32<<<dim3(QDIM / 128, SEQ / 128), 256>>>(x, wq_w, wq_b, q, SEQ, QDIM, DIM);
    gemm_tf32<<<dim3(KVDIM / 128, SEQ / 128), 256>>>(x, wk_w, wk_b, k, SEQ, KVDIM, DIM);
    gemm_tf32<<<dim3(KVDIM / 128, SEQ / 128), 256>>>(x, wv_w, wv_b, v, SEQ, KVDIM, DIM);

    // RoPE on q (64 heads) and k (8 heads)
    rope_kernel<<<(SEQ * NH * 32 + 255) / 256, 256>>>(q, rope, NH);
    rope_kernel<<<(SEQ * NKV * 32 + 255) / 256, 256>>>(k, rope, NKV);

    // Sliding-window attention with sink gating
    attn_kernel<<<SEQ * NH / 4, 128>>>(q, k, v, sinks, attn);

    // Output projection
    gemm_tf32<<<dim3((DIM + 127) / 128, SEQ / 128), 256>>>(attn, wo_w, wo_b, out, SEQ, DIM, QDIM);
}

// round 3
// speedup vs baseline: 3.2710x; 1.0395x over previous
#include <cuda_runtime.h>
#include <cuda_bf16.h>
#include <math.h>

#define SEQ 2048
#define DIM 2880
#define NH 64
#define NKV 8
#define HD 64
#define QDIM (NH*HD)     // 4096
#define KVDIM (NKV*HD)   // 512
#define WINDOW 128

typedef __nv_bfloat16 bf16;

// fp32 scratch
__device__ float g_q[SEQ * QDIM];
__device__ float g_k[SEQ * KVDIM];
__device__ float g_v[SEQ * KVDIM];
__device__ float g_attn[SEQ * QDIM];

// bf16 hi/lo split scratch
__device__ bf16 g_xh[SEQ * DIM],     g_xl[SEQ * DIM];
__device__ bf16 g_wqh[QDIM * DIM],   g_wql[QDIM * DIM];
__device__ bf16 g_wkh[KVDIM * DIM],  g_wkl[KVDIM * DIM];
__device__ bf16 g_wvh[KVDIM * DIM],  g_wvl[KVDIM * DIM];
__device__ bf16 g_woh[DIM * QDIM],   g_wol[DIM * QDIM];
__device__ bf16 g_ah[SEQ * QDIM],    g_al[SEQ * QDIM];

// ---------------------------------------------------------------------------
// split fp32 -> bf16 hi + bf16 lo
// ---------------------------------------------------------------------------
__global__ void split_bf16(const float* __restrict__ src,
                           bf16* __restrict__ hi, bf16* __restrict__ lo, int n)
{
    int i = (blockIdx.x * blockDim.x + threadIdx.x) * 4;
    if (i >= n) return;
    float4 v = *(const float4*)(src + i);
    bf16 h0 = __float2bfloat16_rn(v.x);
    bf16 h1 = __float2bfloat16_rn(v.y);
    bf16 h2 = __float2bfloat16_rn(v.z);
    bf16 h3 = __float2bfloat16_rn(v.w);
    bf16 l0 = __float2bfloat16_rn(v.x - __bfloat162float(h0));
    bf16 l1 = __float2bfloat16_rn(v.y - __bfloat162float(h1));
    bf16 l2 = __float2bfloat16_rn(v.z - __bfloat162float(h2));
    bf16 l3 = __float2bfloat16_rn(v.w - __bfloat162float(h3));
    __nv_bfloat162* hp = (__nv_bfloat162*)(hi + i);
    __nv_bfloat162* lp = (__nv_bfloat162*)(lo + i);
    hp[0] = __nv_bfloat162(h0, h1); hp[1] = __nv_bfloat162(h2, h3);
    lp[0] = __nv_bfloat162(l0, l1); lp[1] = __nv_bfloat162(l2, l3);
}

// ---------------------------------------------------------------------------
// bf16x3 tensor-core GEMM (NT): C = Ah*Bh^T + Ah*Bl^T + Al*Bh^T + bias
// Block 128x128, BK=16, 256 thr = 8 warps (4m x 2n), warp tile 32x64.
// cp.async double-buffer, ldmatrix fragment loads, smem row stride 48B.
// Requires M%128==0, K%16==0; N guarded.
// ---------------------------------------------------------------------------
#define RSTRIDE 24   // bf16 per smem row (48 bytes)
#define TILE_BF 3072 // 128 * 24

__global__ __launch_bounds__(256) void gemm_bf16x3(
    const bf16* __restrict__ Ah, const bf16* __restrict__ Al,
    const bf16* __restrict__ Bh, const bf16* __restrict__ Bl,
    const float* __restrict__ bias, float* __restrict__ C,
    int M, int N, int K)
{
    // stages(2) x tiles(Ah,Al,Bh,Bl) x 128 x 24 bf16 = 49152 B
    __shared__ bf16 sm[2 * 4 * TILE_BF];

    const int tid  = threadIdx.x;
    const int bm   = blockIdx.y * 128;
    const int bn   = blockIdx.x * 128;
    const int wid  = tid >> 5;
    const int lane = tid & 31;
    const int wm   = (wid & 3) * 32;
    const int wn   = (wid >> 2) * 64;
    const int g    = lane >> 2;
    const int tg   = lane & 3;

    unsigned smem_u32;
    { unsigned long long t = __cvta_generic_to_shared(sm); smem_u32 = (unsigned)t; }

    // cp.async mapping: thread -> (row, 8-elem segment)
    const int crow = tid >> 1;
    const int cseg = (tid & 1) * 8;
    const long aoff = (long)(bm + crow) * K + cseg;
    const int brow  = bn + crow;
    const int bvld  = (brow < N) ? 16 : 0;
    const long boff = (long)((brow < N) ? brow : (N - 1)) * K + cseg;
    const unsigned dsto = (unsigned)(crow * RSTRIDE + cseg) * 2u; // bytes in tile

    const int KT = K / 16;

#define ISSUE_STAGE(s, k0)                                                     \
    do {                                                                       \
        unsigned b_ = smem_u32 + (unsigned)((s) * 4 * TILE_BF * 2) + dsto;     \
        asm volatile("cp.async.cg.shared.global [%0], [%1], 16;\n"             \
                     :: "r"(b_), "l"(Ah + aoff + (k0)));                       \
        asm volatile("cp.async.cg.shared.global [%0], [%1], 16;\n"             \
                     :: "r"(b_ + TILE_BF * 2), "l"(Al + aoff + (k0)));         \
        asm volatile("cp.async.cg.shared.global [%0], [%1], 16, %2;\n"         \
                     :: "r"(b_ + 2 * TILE_BF * 2), "l"(Bh + boff + (k0)), "r"(bvld)); \
        asm volatile("cp.async.cg.shared.global [%0], [%1], 16, %2;\n"         \
                     :: "r"(b_ + 3 * TILE_BF * 2), "l"(Bl + boff + (k0)), "r"(bvld)); \
        asm volatile("cp.async.commit_group;\n");                              \
    } while (0)

    float acc[2][8][4];
#pragma unroll
    for (int mi = 0; mi < 2; mi++)
#pragma unroll
        for (int ni = 0; ni < 8; ni++)
#pragma unroll
            for (int r = 0; r < 4; r++) acc[mi][ni][r] = 0.f;

    ISSUE_STAGE(0, 0);

    // ldmatrix lane addressing (within a tile, bytes)
    const unsigned a_rowsel = ((lane >> 3) & 1) * 8 + (lane & 7);
    const unsigned a_koff   = ((lane >> 4) & 1) * 16;
    const unsigned b_rowsel = ((lane >> 4) & 1) * 8 + (lane & 7);
    const unsigned b_koff   = ((lane >> 3) & 1) * 16;

    for (int kt = 0; kt < KT; kt++) {
        asm volatile("cp.async.wait_group 0;\n");
        __syncthreads();
        if (kt + 1 < KT) ISSUE_STAGE((kt + 1) & 1, (kt + 1) * 16);

        const unsigned stb = smem_u32 + (unsigned)((kt & 1) * 4 * TILE_BF * 2);
        unsigned fAh[2][4], fAl[2][4], fBh[8][2], fBl[8][2];

#pragma unroll
        for (int mi = 0; mi < 2; mi++) {
            unsigned addr = stb + (wm + mi * 16 + a_rowsel) * 48 + a_koff;
            asm volatile("ldmatrix.sync.aligned.m8n8.x4.shared.b16 {%0,%1,%2,%3}, [%4];"
                : "=r"(fAh[mi][0]), "=r"(fAh[mi][1]), "=r"(fAh[mi][2]), "=r"(fAh[mi][3])
                : "r"(addr));
            asm volatile("ldmatrix.sync.aligned.m8n8.x4.shared.b16 {%0,%1,%2,%3}, [%4];"
                : "=r"(fAl[mi][0]), "=r"(fAl[mi][1]), "=r"(fAl[mi][2]), "=r"(fAl[mi][3])
                : "r"(addr + TILE_BF * 2));
        }
#pragma unroll
        for (int p = 0; p < 4; p++) {
            unsigned addr = stb + 2u * TILE_BF * 2 + (wn + p * 16 + b_rowsel) * 48 + b_koff;
            asm volatile("ldmatrix.sync.aligned.m8n8.x4.shared.b16 {%0,%1,%2,%3}, [%4];"
                : "=r"(fBh[2*p][0]), "=r"(fBh[2*p][1]), "=r"(fBh[2*p+1][0]), "=r"(fBh[2*p+1][1])
                : "r"(addr));
            asm volatile("ldmatrix.sync.aligned.m8n8.x4.shared.b16 {%0,%1,%2,%3}, [%4];"
                : "=r"(fBl[2*p][0]), "=r"(fBl[2*p][1]), "=r"(fBl[2*p+1][0]), "=r"(fBl[2*p+1][1])
                : "r"(addr + TILE_BF * 2));
        }

#define MMA(d, a, b)                                                           \
    asm volatile("mma.sync.aligned.m16n8k16.row.col.f32.bf16.bf16.f32 "        \
                 "{%0,%1,%2,%3}, {%4,%5,%6,%7}, {%8,%9}, {%0,%1,%2,%3};"       \
                 : "+f"((d)[0]), "+f"((d)[1]), "+f"((d)[2]), "+f"((d)[3])      \
                 : "r"((a)[0]), "r"((a)[1]), "r"((a)[2]), "r"((a)[3]),         \
                   "r"((b)[0]), "r"((b)[1]))

#pragma unroll
        for (int ni = 0; ni < 8; ni++)
#pragma unroll
            for (int mi = 0; mi < 2; mi++)
                MMA(acc[mi][ni], fAh[mi], fBh[ni]);
#pragma unroll
        for (int ni = 0; ni < 8; ni++)
#pragma unroll
            for (int mi = 0; mi < 2; mi++)
                MMA(acc[mi][ni], fAh[mi], fBl[ni]);
#pragma unroll
        for (int ni = 0; ni < 8; ni++)
#pragma unroll
            for (int mi = 0; mi < 2; mi++)
                MMA(acc[mi][ni], fAl[mi], fBh[ni]);

        __syncthreads();
    }

    // epilogue
#pragma unroll
    for (int mi = 0; mi < 2; mi++) {
        const int row = bm + wm + mi * 16 + g;
#pragma unroll
        for (int ni = 0; ni < 8; ni++) {
            const int col = bn + wn + ni * 8 + tg * 2;
            if (col < N) {
                const float bx = bias[col], by = bias[col + 1];
                float2 v0 = make_float2(acc[mi][ni][0] + bx, acc[mi][ni][1] + by);
                float2 v1 = make_float2(acc[mi][ni][2] + bx, acc[mi][ni][3] + by);
                *(float2*)(C + (size_t)row * N + col)       = v0;
                *(float2*)(C + (size_t)(row + 8) * N + col) = v1;
            }
        }
    }
#undef MMA
#undef ISSUE_STAGE
}

// ---------------------------------------------------------------------------
// RoPE, in-place on [SEQ, n_heads, 64].
// ---------------------------------------------------------------------------
__global__ void rope_kernel(float* __restrict__ t, const float* __restrict__ rope,
                            int n_heads)
{
    const int idx = blockIdx.x * blockDim.x + threadIdx.x;
    const int total = SEQ * n_heads * 32;
    if (idx >= total) return;
    const int d = idx & 31;
    const int h = (idx >> 5) % n_heads;
    const int s = idx / (32 * n_heads);

    const float c1 = rope[s * 128 + d];
    const float c2 = rope[s * 128 + d + 32];
    const float s1 = rope[s * 128 + 64 + d];
    const float s2 = rope[s * 128 + 96 + d];

    float* base = t + ((size_t)s * n_heads + h) * HD;
    const float x1 = base[d];
    const float x2 = base[d + 32];
    base[d]      = x1 * c1 - x2 * s1;
    base[d + 32] = x2 * c2 + x1 * s2;
}

// ---------------------------------------------------------------------------
// Sliding-window attention + sink gating. One warp per (query, head).
// ---------------------------------------------------------------------------
__global__ __launch_bounds__(128) void attn_kernel(
    const float* __restrict__ q, const float* __restrict__ k,
    const float* __restrict__ v, const float* __restrict__ sinks,
    float* __restrict__ out)
{
    const float scale = 0.16832169945461f;  // (0.1*ln(32)+1)/8
    const int w    = threadIdx.x >> 5;
    const int lane = threadIdx.x & 31;
    const int p = blockIdx.x * 4 + w;
    const int i = p & (SEQ - 1);
    const int h = p >> 11;

    __shared__ float shq[4][64];
    __shared__ float shp[4][128];

    const float* qrow = q + (size_t)i * QDIM + h * HD;
    shq[w][lane]      = qrow[lane];
    shq[w][lane + 32] = qrow[lane + 32];
    __syncwarp();

    const int kvh = h >> 3;
    int start = i - (WINDOW - 1); if (start < 0) start = 0;
    const int cnt = i - start + 1;

    float sc[4];
#pragma unroll
    for (int t = 0; t < 4; t++) {
        const int jj = lane + 32 * t;
        if (jj < cnt) {
            const float4* krow =
                (const float4*)(k + (size_t)(start + jj) * KVDIM + kvh * HD);
            float s = 0.f;
#pragma unroll
            for (int d4 = 0; d4 < 16; d4++) {
                const float4 kk = krow[d4];
                s = fmaf(kk.x, shq[w][d4 * 4 + 0], s);
                s = fmaf(kk.y, shq[w][d4 * 4 + 1], s);
                s = fmaf(kk.z, shq[w][d4 * 4 + 2], s);
                s = fmaf(kk.w, shq[w][d4 * 4 + 3], s);
            }
            sc[t] = s * scale;
        } else {
            sc[t] = -1e30f;
        }
    }

    float m = fmaxf(fmaxf(sc[0], sc[1]), fmaxf(sc[2], sc[3]));
#pragma unroll
    for (int o = 16; o; o >>= 1) m = fmaxf(m, __shfl_xor_sync(0xffffffffu, m, o));

    float e[4], sum = 0.f;
#pragma unroll
    for (int t = 0; t < 4; t++) { e[t] = expf(sc[t] - m); sum += e[t]; }
#pragma unroll
    for (int o = 16; o; o >>= 1) sum += __shfl_xor_sync(0xffffffffu, sum, o);

    const float lse  = m + logf(sum);
    const float sig  = 1.f / (1.f + expf(sinks[h] - lse));
    const float wsc  = sig / sum;
#pragma unroll
    for (int t = 0; t < 4; t++) shp[w][lane + 32 * t] = e[t] * wsc;
    __syncwarp();

    float acc0 = 0.f, acc1 = 0.f;
    for (int jj = 0; jj < cnt; jj++) {
        const float pj = shp[w][jj];
        const float* vrow = v + (size_t)(start + jj) * KVDIM + kvh * HD;
        acc0 = fmaf(pj, vrow[lane], acc0);
        acc1 = fmaf(pj, vrow[lane + 32], acc1);
    }
    float* orow = out + (size_t)i * QDIM + h * HD;
    orow[lane]      = acc0;
    orow[lane + 32] = acc1;
}

// ---------------------------------------------------------------------------
extern "C" void kernel_launch(void* const* d_in, const int* in_sizes, int n_in,
                              void* d_out, int out_size)
{
    const float* x     = (const float*)d_in[0];
    const float* rope  = (const float*)d_in[1];
    const float* wq_w  = (const float*)d_in[2];
    const float* wq_b  = (const float*)d_in[3];
    const float* wk_w  = (const float*)d_in[4];
    const float* wk_b  = (const float*)d_in[5];
    const float* wv_w  = (const float*)d_in[6];
    const float* wv_b  = (const float*)d_in[7];
    const float* wo_w  = (const float*)d_in[8];
    const float* wo_b  = (const float*)d_in[9];
    const float* sinks = (const float*)d_in[10];
    float* out = (float*)d_out;

    float *q, *k, *v, *attn;
    cudaGetSymbolAddress((void**)&q, g_q);
    cudaGetSymbolAddress((void**)&k, g_k);
    cudaGetSymbolAddress((void**)&v, g_v);
    cudaGetSymbolAddress((void**)&attn, g_attn);

    bf16 *xh, *xl, *wqh, *wql, *wkh, *wkl, *wvh, *wvl, *woh, *wol, *ah, *al;
    cudaGetSymbolAddress((void**)&xh, g_xh);   cudaGetSymbolAddress((void**)&xl, g_xl);
    cudaGetSymbolAddress((void**)&wqh, g_wqh); cudaGetSymbolAddress((void**)&wql, g_wql);
    cudaGetSymbolAddress((void**)&wkh, g_wkh); cudaGetSymbolAddress((void**)&wkl, g_wkl);
    cudaGetSymbolAddress((void**)&wvh, g_wvh); cudaGetSymbolAddress((void**)&wvl, g_wvl);
    cudaGetSymbolAddress((void**)&woh, g_woh); cudaGetSymbolAddress((void**)&wol, g_wol);
    cudaGetSymbolAddress((void**)&ah, g_ah);   cudaGetSymbolAddress((void**)&al, g_al);

    // splits (fp32 -> bf16 hi/lo)
    #define SPLIT(src, h_, l_, n) \
        split_bf16<<<((n)/4 + 255)/256, 256>>>(src, h_, l_, n)
    SPLIT(x,    xh,  xl,  SEQ * DIM);
    SPLIT(wq_w, wqh, wql, QDIM * DIM);
    SPLIT(wk_w, wkh, wkl, KVDIM * DIM);
    SPLIT(wv_w, wvh, wvl, KVDIM * DIM);
    SPLIT(wo_w, woh, wol, DIM * QDIM);

    // QKV projections (bf16x3 tensor cores)
    gemm_bf16x3<<<dim3(QDIM / 128, SEQ / 128), 256>>>(xh, xl, wqh, wql, wq_b, q, SEQ, QDIM, DIM);
    gemm_bf16x3<<<dim3(KVDIM / 128, SEQ / 128), 256>>>(xh, xl, wkh, wkl, wk_b, k, SEQ, KVDIM, DIM);
    gemm_bf16x3<<<dim3(KVDIM / 128, SEQ / 128), 256>>>(xh, xl, wvh, wvl, wv_b, v, SEQ, KVDIM, DIM);

    // RoPE
    rope_kernel<<<(SEQ * NH * 32 + 255) / 256, 256>>>(q, rope, NH);
    rope_kernel<<<(SEQ * NKV * 32 + 255) / 256, 256>>>(k, rope, NKV);

    // attention
    attn_kernel<<<SEQ * NH / 4, 128>>>(q, k, v, sinks, attn);

    // split attention output, then O-projection
    SPLIT(attn, ah, al, SEQ * QDIM);
    gemm_bf16x3<<<dim3((DIM + 127) / 128, SEQ / 128), 256>>>(ah, al, woh, wol, wo_b, out, SEQ, DIM, QDIM);
    #undef SPLIT
}

// round 5
// speedup vs baseline: 3.9572x; 1.2098x over previous
#include <cuda_runtime.h>
#include <cuda_bf16.h>
#include <math.h>

#define SEQ 2048
#define DIM 2880
#define NH 64
#define NKV 8
#define HD 64
#define QDIM (NH*HD)     // 4096
#define KVDIM (NKV*HD)   // 512
#define WINDOW 128

typedef __nv_bfloat16 bf16;

// fp32 scratch
__device__ float g_q[SEQ * QDIM];
__device__ float g_k[SEQ * KVDIM];
__device__ float g_v[SEQ * KVDIM];
__device__ float g_attn[SEQ * QDIM];

// bf16 hi/lo split scratch
__device__ bf16 g_xh[SEQ * DIM],     g_xl[SEQ * DIM];
__device__ bf16 g_wqh[QDIM * DIM],   g_wql[QDIM * DIM];
__device__ bf16 g_wkh[KVDIM * DIM],  g_wkl[KVDIM * DIM];
__device__ bf16 g_wvh[KVDIM * DIM],  g_wvl[KVDIM * DIM];
__device__ bf16 g_woh[DIM * QDIM],   g_wol[DIM * QDIM];
__device__ bf16 g_ah[SEQ * QDIM],    g_al[SEQ * QDIM];

// ---------------------------------------------------------------------------
// split fp32 -> bf16 hi + bf16 lo
// ---------------------------------------------------------------------------
__global__ void split_bf16(const float* __restrict__ src,
                           bf16* __restrict__ hi, bf16* __restrict__ lo, int n)
{
    int i = (blockIdx.x * blockDim.x + threadIdx.x) * 4;
    if (i >= n) return;
    float4 v = *(const float4*)(src + i);
    bf16 h0 = __float2bfloat16_rn(v.x);
    bf16 h1 = __float2bfloat16_rn(v.y);
    bf16 h2 = __float2bfloat16_rn(v.z);
    bf16 h3 = __float2bfloat16_rn(v.w);
    bf16 l0 = __float2bfloat16_rn(v.x - __bfloat162float(h0));
    bf16 l1 = __float2bfloat16_rn(v.y - __bfloat162float(h1));
    bf16 l2 = __float2bfloat16_rn(v.z - __bfloat162float(h2));
    bf16 l3 = __float2bfloat16_rn(v.w - __bfloat162float(h3));
    __nv_bfloat162* hp = (__nv_bfloat162*)(hi + i);
    __nv_bfloat162* lp = (__nv_bfloat162*)(lo + i);
    hp[0] = __nv_bfloat162(h0, h1); hp[1] = __nv_bfloat162(h2, h3);
    lp[0] = __nv_bfloat162(l0, l1); lp[1] = __nv_bfloat162(l2, l3);
}

// ---------------------------------------------------------------------------
// bf16x3 mma.sync GEMM (NT): C = Ah*Bh^T + Ah*Bl^T + Al*Bh^T + bias
// Block 128x128, BK=32, 3-stage cp.async ring (wait_group 1), XOR-swizzled
// 64B smem rows (conflict-free cp.async stores + ldmatrix), 256 thr = 8 warps
// (4m x 2n), warp tile 32x64. Requires M%128==0, K%32==0; N guarded.
// ---------------------------------------------------------------------------
#define TILEB 8192u                 // one operand tile: 128 rows x 64 bytes
#define STAGEB (4u*TILEB)           // Ah, Al, Bh, Bl = 32 KB
#define NSTG 3
#define GSMEM_BYTES (NSTG*STAGEB)   // 96 KB

__device__ __forceinline__ void cpa16(unsigned dst, const void* src) {
    asm volatile("cp.async.cg.shared.global [%0], [%1], 16;" :: "r"(dst), "l"(src));
}
__device__ __forceinline__ void cpa16p(unsigned dst, const void* src, int sz) {
    asm volatile("cp.async.cg.shared.global [%0], [%1], 16, %2;"
                 :: "r"(dst), "l"(src), "r"(sz));
}

__global__ __launch_bounds__(256) void gemm_bf16x3(
    const bf16* __restrict__ Ah, const bf16* __restrict__ Al,
    const bf16* __restrict__ Bh, const bf16* __restrict__ Bl,
    const float* __restrict__ bias, float* __restrict__ C,
    int M, int N, int K)
{
    extern __shared__ char dsm[];
    unsigned sb;
    { unsigned long long t = __cvta_generic_to_shared(dsm); sb = (unsigned)t; }

    const int tid  = threadIdx.x;
    const int wid  = tid >> 5;
    const int lane = tid & 31;
    const int bm   = blockIdx.y * 128;
    const int bn   = blockIdx.x * 128;
    const int wm   = (wid & 3) * 32;
    const int wn   = (wid >> 2) * 64;
    const int g    = lane >> 2;
    const int tg   = lane & 3;

    const int KT = K / 32;

    // cp.async mapping: 512 x 16B per tile, 2 chunks per thread
    const int r0c = tid >> 2;            // rows 0..63 (chunk 0), +64 (chunk 1)
    const int c0c = tid & 3;             // 16B segment 0..3

#define SWOFF(r, c) ((unsigned)((r) * 64 + ((((c) ^ (((r) >> 1) & 3))) << 4)))

#define ISSUE_STAGE(sidx, k0)                                                  \
    do {                                                                       \
        const unsigned tb = sb + (unsigned)(sidx) * STAGEB;                    \
        _Pragma("unroll")                                                      \
        for (int it = 0; it < 2; it++) {                                       \
            const int r = r0c + it * 64;                                       \
            const unsigned so = SWOFF(r, c0c);                                 \
            const size_t ao = (size_t)(bm + r) * K + (k0) + c0c * 8;           \
            const int brw = bn + r;                                            \
            const int pz  = (brw < N) ? 16 : 0;                                \
            const size_t bo = (size_t)((brw < N) ? brw : 0) * K + (k0) + c0c * 8; \
            cpa16 (tb + so,             Ah + ao);                              \
            cpa16 (tb + TILEB + so,     Al + ao);                              \
            cpa16p(tb + 2 * TILEB + so, Bh + bo, pz);                          \
            cpa16p(tb + 3 * TILEB + so, Bl + bo, pz);                          \
        }                                                                      \
        asm volatile("cp.async.commit_group;");                                \
    } while (0)

    float acc[2][8][4];
#pragma unroll
    for (int mi = 0; mi < 2; mi++)
#pragma unroll
        for (int ni = 0; ni < 8; ni++)
#pragma unroll
            for (int r = 0; r < 4; r++) acc[mi][ni][r] = 0.f;

    ISSUE_STAGE(0, 0);
    ISSUE_STAGE(1, 32);

    // ldmatrix lane addressing
    const int a_row = ((lane >> 3) & 1) * 8 + (lane & 7);  // row within m16
    const int a_ch  = (lane >> 4) & 1;                     // k 16B-seg within k16
    const int b_row = ((lane >> 4) & 1) * 8 + (lane & 7);
    const int b_ch  = (lane >> 3) & 1;

    for (int kt = 0; kt < KT; kt++) {
        asm volatile("cp.async.wait_group %0;" :: "n"(1));
        __syncthreads();

        if (kt + 2 < KT) ISSUE_STAGE((kt + 2) % NSTG, (kt + 2) * 32);
        else             asm volatile("cp.async.commit_group;");

        const unsigned stb = sb + (unsigned)(kt % NSTG) * STAGEB;

#pragma unroll
        for (int ks = 0; ks < 2; ks++) {
            unsigned fAh[2][4], fAl[2][4], fBh[8][2], fBl[8][2];
            const int ca = ks * 2 + a_ch;
            const int cb = ks * 2 + b_ch;

#pragma unroll
            for (int mi = 0; mi < 2; mi++) {
                const int r = wm + mi * 16 + a_row;
                const unsigned ad = stb + SWOFF(r, ca);
                asm volatile("ldmatrix.sync.aligned.m8n8.x4.shared.b16 {%0,%1,%2,%3}, [%4];"
                    : "=r"(fAh[mi][0]), "=r"(fAh[mi][1]), "=r"(fAh[mi][2]), "=r"(fAh[mi][3])
                    : "r"(ad));
                asm volatile("ldmatrix.sync.aligned.m8n8.x4.shared.b16 {%0,%1,%2,%3}, [%4];"
                    : "=r"(fAl[mi][0]), "=r"(fAl[mi][1]), "=r"(fAl[mi][2]), "=r"(fAl[mi][3])
                    : "r"(ad + TILEB));
            }
#pragma unroll
            for (int p = 0; p < 4; p++) {
                const int r = wn + p * 16 + b_row;
                const unsigned bd = stb + 2u * TILEB + SWOFF(r, cb);
                asm volatile("ldmatrix.sync.aligned.m8n8.x4.shared.b16 {%0,%1,%2,%3}, [%4];"
                    : "=r"(fBh[2*p][0]), "=r"(fBh[2*p][1]), "=r"(fBh[2*p+1][0]), "=r"(fBh[2*p+1][1])
                    : "r"(bd));
                asm volatile("ldmatrix.sync.aligned.m8n8.x4.shared.b16 {%0,%1,%2,%3}, [%4];"
                    : "=r"(fBl[2*p][0]), "=r"(fBl[2*p][1]), "=r"(fBl[2*p+1][0]), "=r"(fBl[2*p+1][1])
                    : "r"(bd + TILEB));
            }

#define MMA(d, a, b)                                                           \
    asm volatile("mma.sync.aligned.m16n8k16.row.col.f32.bf16.bf16.f32 "        \
                 "{%0,%1,%2,%3}, {%4,%5,%6,%7}, {%8,%9}, {%0,%1,%2,%3};"       \
                 : "+f"((d)[0]), "+f"((d)[1]), "+f"((d)[2]), "+f"((d)[3])      \
                 : "r"((a)[0]), "r"((a)[1]), "r"((a)[2]), "r"((a)[3]),         \
                   "r"((b)[0]), "r"((b)[1]))

#pragma unroll
            for (int ni = 0; ni < 8; ni++)
#pragma unroll
                for (int mi = 0; mi < 2; mi++)
                    MMA(acc[mi][ni], fAh[mi], fBh[ni]);
#pragma unroll
            for (int ni = 0; ni < 8; ni++)
#pragma unroll
                for (int mi = 0; mi < 2; mi++)
                    MMA(acc[mi][ni], fAh[mi], fBl[ni]);
#pragma unroll
            for (int ni = 0; ni < 8; ni++)
#pragma unroll
                for (int mi = 0; mi < 2; mi++)
                    MMA(acc[mi][ni], fAl[mi], fBh[ni]);
#undef MMA
        }
    }

    // epilogue
#pragma unroll
    for (int mi = 0; mi < 2; mi++) {
        const int row = bm + wm + mi * 16 + g;
#pragma unroll
        for (int ni = 0; ni < 8; ni++) {
            const int col = bn + wn + ni * 8 + tg * 2;
            if (col < N) {
                const float bx = bias[col], by = bias[col + 1];
                float2 v0 = make_float2(acc[mi][ni][0] + bx, acc[mi][ni][1] + by);
                float2 v1 = make_float2(acc[mi][ni][2] + bx, acc[mi][ni][3] + by);
                *(float2*)(C + (size_t)row * N + col)       = v0;
                *(float2*)(C + (size_t)(row + 8) * N + col) = v1;
            }
        }
    }
#undef ISSUE_STAGE
#undef SWOFF
}

// ---------------------------------------------------------------------------
// RoPE, in-place on [SEQ, n_heads, 64].
// ---------------------------------------------------------------------------
__global__ void rope_kernel(float* __restrict__ t, const float* __restrict__ rope,
                            int n_heads)
{
    const int idx = blockIdx.x * blockDim.x + threadIdx.x;
    const int total = SEQ * n_heads * 32;
    if (idx >= total) return;
    const int d = idx & 31;
    const int h = (idx >> 5) % n_heads;
    const int s = idx / (32 * n_heads);

    const float c1 = rope[s * 128 + d];
    const float c2 = rope[s * 128 + d + 32];
    const float s1 = rope[s * 128 + 64 + d];
    const float s2 = rope[s * 128 + 96 + d];

    float* base = t + ((size_t)s * n_heads + h) * HD;
    const float x1 = base[d];
    const float x2 = base[d + 32];
    base[d]      = x1 * c1 - x2 * s1;
    base[d + 32] = x2 * c2 + x1 * s2;
}

// ---------------------------------------------------------------------------
// Sliding-window attention + sink gating. One warp per (query, head).
// ---------------------------------------------------------------------------
__global__ __launch_bounds__(128) void attn_kernel(
    const float* __restrict__ q, const float* __restrict__ k,
    const float* __restrict__ v, const float* __restrict__ sinks,
    float* __restrict__ out)
{
    const float scale = 0.16832169945461f;  // (0.1*ln(32)+1)/8
    const int w    = threadIdx.x >> 5;
    const int lane = threadIdx.x & 31;
    const int p = blockIdx.x * 4 + w;
    const int i = p & (SEQ - 1);
    const int h = p >> 11;

    __shared__ float shq[4][64];
    __shared__ float shp[4][128];

    const float* qrow = q + (size_t)i * QDIM + h * HD;
    shq[w][lane]      = qrow[lane];
    shq[w][lane + 32] = qrow[lane + 32];
    __syncwarp();

    const int kvh = h >> 3;
    int start = i - (WINDOW - 1); if (start < 0) start = 0;
    const int cnt = i - start + 1;

    float sc[4];
#pragma unroll
    for (int t = 0; t < 4; t++) {
        const int jj = lane + 32 * t;
        if (jj < cnt) {
            const float4* krow =
                (const float4*)(k + (size_t)(start + jj) * KVDIM + kvh * HD);
            float s = 0.f;
#pragma unroll
            for (int d4 = 0; d4 < 16; d4++) {
                const float4 kk = krow[d4];
                s = fmaf(kk.x, shq[w][d4 * 4 + 0], s);
                s = fmaf(kk.y, shq[w][d4 * 4 + 1], s);
                s = fmaf(kk.z, shq[w][d4 * 4 + 2], s);
                s = fmaf(kk.w, shq[w][d4 * 4 + 3], s);
            }
            sc[t] = s * scale;
        } else {
            sc[t] = -1e30f;
        }
    }

    float m = fmaxf(fmaxf(sc[0], sc[1]), fmaxf(sc[2], sc[3]));
#pragma unroll
    for (int o = 16; o; o >>= 1) m = fmaxf(m, __shfl_xor_sync(0xffffffffu, m, o));

    float e[4], sum = 0.f;
#pragma unroll
    for (int t = 0; t < 4; t++) { e[t] = expf(sc[t] - m); sum += e[t]; }
#pragma unroll
    for (int o = 16; o; o >>= 1) sum += __shfl_xor_sync(0xffffffffu, sum, o);

    const float lse  = m + logf(sum);
    const float sig  = 1.f / (1.f + expf(sinks[h] - lse));
    const float wsc  = sig / sum;
#pragma unroll
    for (int t = 0; t < 4; t++) shp[w][lane + 32 * t] = e[t] * wsc;
    __syncwarp();

    float acc0 = 0.f, acc1 = 0.f;
    for (int jj = 0; jj < cnt; jj++) {
        const float pj = shp[w][jj];
        const float* vrow = v + (size_t)(start + jj) * KVDIM + kvh * HD;
        acc0 = fmaf(pj, vrow[lane], acc0);
        acc1 = fmaf(pj, vrow[lane + 32], acc1);
    }
    float* orow = out + (size_t)i * QDIM + h * HD;
    orow[lane]      = acc0;
    orow[lane + 32] = acc1;
}

// ---------------------------------------------------------------------------
extern "C" void kernel_launch(void* const* d_in, const int* in_sizes, int n_in,
                              void* d_out, int out_size)
{
    const float* x     = (const float*)d_in[0];
    const float* rope  = (const float*)d_in[1];
    const float* wq_w  = (const float*)d_in[2];
    const float* wq_b  = (const float*)d_in[3];
    const float* wk_w  = (const float*)d_in[4];
    const float* wk_b  = (const float*)d_in[5];
    const float* wv_w  = (const float*)d_in[6];
    const float* wv_b  = (const float*)d_in[7];
    const float* wo_w  = (const float*)d_in[8];
    const float* wo_b  = (const float*)d_in[9];
    const float* sinks = (const float*)d_in[10];
    float* out = (float*)d_out;

    float *q, *k, *v, *attn;
    cudaGetSymbolAddress((void**)&q, g_q);
    cudaGetSymbolAddress((void**)&k, g_k);
    cudaGetSymbolAddress((void**)&v, g_v);
    cudaGetSymbolAddress((void**)&attn, g_attn);

    bf16 *xh, *xl, *wqh, *wql, *wkh, *wkl, *wvh, *wvl, *woh, *wol, *ah, *al;
    cudaGetSymbolAddress((void**)&xh, g_xh);   cudaGetSymbolAddress((void**)&xl, g_xl);
    cudaGetSymbolAddress((void**)&wqh, g_wqh); cudaGetSymbolAddress((void**)&wql, g_wql);
    cudaGetSymbolAddress((void**)&wkh, g_wkh); cudaGetSymbolAddress((void**)&wkl, g_wkl);
    cudaGetSymbolAddress((void**)&wvh, g_wvh); cudaGetSymbolAddress((void**)&wvl, g_wvl);
    cudaGetSymbolAddress((void**)&woh, g_woh); cudaGetSymbolAddress((void**)&wol, g_wol);
    cudaGetSymbolAddress((void**)&ah, g_ah);   cudaGetSymbolAddress((void**)&al, g_al);

    cudaFuncSetAttribute(gemm_bf16x3, cudaFuncAttributeMaxDynamicSharedMemorySize,
                         GSMEM_BYTES);

    #define SPLIT(src, h_, l_, n) \
        split_bf16<<<((n)/4 + 255)/256, 256>>>(src, h_, l_, n)
    SPLIT(x,    xh,  xl,  SEQ * DIM);
    SPLIT(wq_w, wqh, wql, QDIM * DIM);
    SPLIT(wk_w, wkh, wkl, KVDIM * DIM);
    SPLIT(wv_w, wvh, wvl, KVDIM * DIM);
    SPLIT(wo_w, woh, wol, DIM * QDIM);

    // QKV projections (bf16x3 tensor cores)
    gemm_bf16x3<<<dim3(QDIM / 128, SEQ / 128), 256, GSMEM_BYTES>>>(
        xh, xl, wqh, wql, wq_b, q, SEQ, QDIM, DIM);
    gemm_bf16x3<<<dim3(KVDIM / 128, SEQ / 128), 256, GSMEM_BYTES>>>(
        xh, xl, wkh, wkl, wk_b, k, SEQ, KVDIM, DIM);
    gemm_bf16x3<<<dim3(KVDIM / 128, SEQ / 128), 256, GSMEM_BYTES>>>(
        xh, xl, wvh, wvl, wv_b, v, SEQ, KVDIM, DIM);

    // RoPE
    rope_kernel<<<(SEQ * NH * 32 + 255) / 256, 256>>>(q, rope, NH);
    rope_kernel<<<(SEQ * NKV * 32 + 255) / 256, 256>>>(k, rope, NKV);

    // attention
    attn_kernel<<<SEQ * NH / 4, 128>>>(q, k, v, sinks, attn);

    // split attention output, then O-projection
    SPLIT(attn, ah, al, SEQ * QDIM);
    gemm_bf16x3<<<dim3((DIM + 127) / 128, SEQ / 128), 256, GSMEM_BYTES>>>(
        ah, al, woh, wol, wo_b, out, SEQ, DIM, QDIM);
    #undef SPLIT
}